// round 1
// baseline (speedup 1.0000x reference)
#include <cuda_runtime.h>

#define S 2048
#define B 4
#define H 16
#define DK 64
#define DM 1024
#define MTOT (B*S)
#define SCALE_C 0.125f

#define TQ 128
#define TK 128
#define ATTN_SMEM ((TQ*DK + DK*TK + TK*DK + TQ*TK) * 4)

typedef unsigned long long u64;

__device__ __forceinline__ u64 pk2(float x, float y) {
    u64 r; asm("mov.b64 %0, {%1,%2};" : "=l"(r) : "f"(x), "f"(y)); return r;
}
__device__ __forceinline__ void fma2(u64 &d, u64 a, u64 b) {
    asm("fma.rn.f32x2 %0, %1, %2, %0;" : "+l"(d) : "l"(a), "l"(b));
}
__device__ __forceinline__ void mul2(u64 &d, u64 a) {
    asm("mul.rn.f32x2 %0, %0, %1;" : "+l"(d) : "l"(a));
}
__device__ __forceinline__ float2 upk(u64 v) {
    float lo, hi; asm("mov.b64 {%0,%1}, %2;" : "=f"(lo), "=f"(hi) : "l"(v));
    return make_float2(lo, hi);
}

// scratch (static device arrays: allowed; no cudaMalloc)
__device__ float g_Q[MTOT * DM];
__device__ float g_K[MTOT * DM];
__device__ float g_V[MTOT * DM];
__device__ float g_A[MTOT * DM];

// ---------------------------------------------------------------------------
// C[m][n] = sum_k A[m][k] * W[n][k] + bias[n]
// A: [M, 1024], W: [1024, 1024] row-major (nn.Linear weight), C: [M, 1024]
// 128x128x16 tiles, 256 threads, 8x8 per-thread tile via f32x2 packed FMA.
// Thread n-columns interleaved {c2, c2+32, c2+64, c2+96} for conflict-free LDS.
// ---------------------------------------------------------------------------
__global__ __launch_bounds__(256, 2) void gemm_bias(
    const float* __restrict__ A, const float* __restrict__ W,
    const float* __restrict__ bias, float* __restrict__ C) {
    __shared__ float As[16][128];
    __shared__ float Ws[16][128];

    const int tid = threadIdx.x;
    const int bm = blockIdx.y * 128;
    const int bn = blockIdx.x * 128;
    const int tm = (tid >> 4) * 8;       // 8 rows, only 2 distinct per warp (broadcast)
    const int c2 = (tid & 15) * 2;       // interleaved column pairs

    u64 acc[8][4];
#pragma unroll
    for (int i = 0; i < 8; i++)
#pragma unroll
        for (int j = 0; j < 4; j++) acc[i][j] = 0ull;

    const float* Ap = A + bm * DM;
    const float* Wp = W + bn * DM;

    for (int k0 = 0; k0 < DM; k0 += 16) {
#pragma unroll
        for (int it = 0; it < 2; it++) {
            int s = tid + it * 256;      // 512 float4 slots per operand
            int row = s >> 2;
            int k4 = (s & 3) << 2;
            float4 av = *(const float4*)(Ap + row * DM + k0 + k4);
            As[k4 + 0][row] = av.x; As[k4 + 1][row] = av.y;
            As[k4 + 2][row] = av.z; As[k4 + 3][row] = av.w;
            float4 wv = *(const float4*)(Wp + row * DM + k0 + k4);
            Ws[k4 + 0][row] = wv.x; Ws[k4 + 1][row] = wv.y;
            Ws[k4 + 2][row] = wv.z; Ws[k4 + 3][row] = wv.w;
        }
        __syncthreads();
#pragma unroll
        for (int kk = 0; kk < 16; kk++) {
            float4 a0 = *(const float4*)&As[kk][tm];
            float4 a1 = *(const float4*)&As[kk][tm + 4];
            u64 ad[8];
            ad[0] = pk2(a0.x, a0.x); ad[1] = pk2(a0.y, a0.y);
            ad[2] = pk2(a0.z, a0.z); ad[3] = pk2(a0.w, a0.w);
            ad[4] = pk2(a1.x, a1.x); ad[5] = pk2(a1.y, a1.y);
            ad[6] = pk2(a1.z, a1.z); ad[7] = pk2(a1.w, a1.w);
            u64 b[4];
#pragma unroll
            for (int j = 0; j < 4; j++) b[j] = *(const u64*)&Ws[kk][c2 + 32 * j];
#pragma unroll
            for (int i = 0; i < 8; i++)
#pragma unroll
                for (int j = 0; j < 4; j++) fma2(acc[i][j], ad[i], b[j]);
        }
        __syncthreads();
    }

#pragma unroll
    for (int i = 0; i < 8; i++) {
        float* crow = C + (bm + tm + i) * DM + bn;
#pragma unroll
        for (int j = 0; j < 4; j++) {
            float2 v = upk(acc[i][j]);
            v.x += bias[bn + c2 + 32 * j];
            v.y += bias[bn + c2 + 32 * j + 1];
            *(float2*)(crow + c2 + 32 * j) = v;
        }
    }
}

// ---------------------------------------------------------------------------
// Flash attention, fp32. One CTA handles (b, h, 128 queries); loops over 16
// key tiles of 128. K transposed in smem (pairs along k for scores), V natural
// (pairs along d for PV). P staged through smem between phases.
// ---------------------------------------------------------------------------
__global__ __launch_bounds__(256, 1) void attn_kernel(
    const float* __restrict__ Q, const float* __restrict__ K,
    const float* __restrict__ V, const int* __restrict__ mask,
    float* __restrict__ O) {
    extern __shared__ float smm[];
    float (*Qs)[DK] = (float(*)[DK])smm;                              // [128][64]
    float (*Kt)[TK] = (float(*)[TK])(smm + TQ * DK);                  // [64][128]
    float (*Vs)[DK] = (float(*)[DK])(smm + TQ * DK + DK * TK);        // [128][64]
    float (*Ps)[TK] = (float(*)[TK])(smm + TQ * DK + 2 * DK * TK);    // [128][128]

    const int tid = threadIdx.x;
    const int qt = blockIdx.x, h = blockIdx.y, b = blockIdx.z;
    const int q0 = qt * TQ;
    const int tq = (tid >> 4) * 8;       // 8 q rows (2 distinct groups per warp)
    const int c2 = (tid & 15) * 2;       // interleaved pairs {c2+32j, c2+32j+1}

    const float* Qb = Q + (b * S + q0) * DM + h * DK;
    const float* Kb = K + (b * S) * DM + h * DK;
    const float* Vb = V + (b * S) * DM + h * DK;
    const int* Mb = mask + (b * S + q0) * S;

    // load Q tile [128][64]
#pragma unroll
    for (int it = 0; it < 8; it++) {
        int s = tid + it * 256;          // 2048 float4 slots
        int row = s >> 4, c4 = (s & 15) << 2;
        *(float4*)&Qs[row][c4] = *(const float4*)(Qb + row * DM + c4);
    }

    float m[8], l[8];
    u64 o2[8][2];
#pragma unroll
    for (int i = 0; i < 8; i++) {
        m[i] = -1e30f; l[i] = 0.f; o2[i][0] = 0ull; o2[i][1] = 0ull;
    }

    for (int kt = 0; kt < S / TK; kt++) {
        __syncthreads();   // prev phase B done (and Q load on first iter)
        // load K transposed: lanes stride along k rows -> conflict-free STS
#pragma unroll
        for (int it = 0; it < 8; it++) {
            int s = tid + it * 256;
            int krow = s & 127;
            int c4 = (s >> 7) << 2;
            float4 kv = *(const float4*)(Kb + (kt * TK + krow) * DM + c4);
            Kt[c4 + 0][krow] = kv.x; Kt[c4 + 1][krow] = kv.y;
            Kt[c4 + 2][krow] = kv.z; Kt[c4 + 3][krow] = kv.w;
        }
        // load V natural [128][64]
#pragma unroll
        for (int it = 0; it < 8; it++) {
            int s = tid + it * 256;
            int row = s >> 4, c4 = (s & 15) << 2;
            *(float4*)&Vs[row][c4] = *(const float4*)(Vb + (kt * TK + row) * DM + c4);
        }
        __syncthreads();

        // ---- phase A: scores S = Q K^T (8 q x 8 k per thread) ----
        u64 acc[8][4];
#pragma unroll
        for (int i = 0; i < 8; i++)
#pragma unroll
            for (int j = 0; j < 4; j++) acc[i][j] = 0ull;

#pragma unroll 4
        for (int d = 0; d < DK; d++) {
            u64 kv[4];
#pragma unroll
            for (int j = 0; j < 4; j++) kv[j] = *(const u64*)&Kt[d][c2 + 32 * j];
#pragma unroll
            for (int i = 0; i < 8; i++) {
                float qv = Qs[tq + i][d];
                u64 qd = pk2(qv, qv);
#pragma unroll
                for (int j = 0; j < 4; j++) fma2(acc[i][j], qd, kv[j]);
            }
        }

        // ---- mask + online softmax (row groups of 16 lanes, shuffle reduce) ----
        const int kbase = kt * TK;
#pragma unroll
        for (int i = 0; i < 8; i++) {
            const int* mrow = Mb + (tq + i) * S + kbase;
            float sc[8];
#pragma unroll
            for (int j = 0; j < 4; j++) {
                float2 v = upk(acc[i][j]);
                int2 mm = *(const int2*)(mrow + c2 + 32 * j);
                sc[2 * j]     = mm.x ? v.x * SCALE_C : -1e9f;
                sc[2 * j + 1] = mm.y ? v.y * SCALE_C : -1e9f;
            }
            float mx = sc[0];
#pragma unroll
            for (int j = 1; j < 8; j++) mx = fmaxf(mx, sc[j]);
            mx = fmaxf(mx, __shfl_xor_sync(0xffffffffu, mx, 1));
            mx = fmaxf(mx, __shfl_xor_sync(0xffffffffu, mx, 2));
            mx = fmaxf(mx, __shfl_xor_sync(0xffffffffu, mx, 4));
            mx = fmaxf(mx, __shfl_xor_sync(0xffffffffu, mx, 8));
            float mn = fmaxf(m[i], mx);
            float corr = __expf(m[i] - mn);
            m[i] = mn;
            float ssum = 0.f;
#pragma unroll
            for (int j = 0; j < 8; j++) { sc[j] = __expf(sc[j] - mn); ssum += sc[j]; }
            ssum += __shfl_xor_sync(0xffffffffu, ssum, 1);
            ssum += __shfl_xor_sync(0xffffffffu, ssum, 2);
            ssum += __shfl_xor_sync(0xffffffffu, ssum, 4);
            ssum += __shfl_xor_sync(0xffffffffu, ssum, 8);
            l[i] = l[i] * corr + ssum;
            u64 cc = pk2(corr, corr);
            mul2(o2[i][0], cc);
            mul2(o2[i][1], cc);
#pragma unroll
            for (int j = 0; j < 4; j++)
                *(float2*)&Ps[tq + i][c2 + 32 * j] = make_float2(sc[2 * j], sc[2 * j + 1]);
        }
        __syncthreads();   // Ps visible

        // ---- phase B: O += P V (8 q x 4 d per thread, d pairs {c2,c2+1,c2+32,c2+33}) ----
#pragma unroll 4
        for (int k = 0; k < TK; k++) {
            u64 v0 = *(const u64*)&Vs[k][c2];
            u64 v1 = *(const u64*)&Vs[k][c2 + 32];
#pragma unroll
            for (int i = 0; i < 8; i++) {
                float p = Ps[tq + i][k];
                u64 pd = pk2(p, p);
                fma2(o2[i][0], pd, v0);
                fma2(o2[i][1], pd, v1);
            }
        }
    }

    // epilogue: normalize and store
#pragma unroll
    for (int i = 0; i < 8; i++) {
        float inv = 1.f / l[i];
        u64 iv = pk2(inv, inv);
        mul2(o2[i][0], iv);
        mul2(o2[i][1], iv);
        float* orow = O + (b * S + q0 + tq + i) * DM + h * DK;
        *(float2*)(orow + c2)      = upk(o2[i][0]);
        *(float2*)(orow + c2 + 32) = upk(o2[i][1]);
    }
}

extern "C" void kernel_launch(void* const* d_in, const int* in_sizes, int n_in,
                              void* d_out, int out_size) {
    const float* x  = (const float*)d_in[0];
    const float* y  = (const float*)d_in[1];
    const int* mask = (const int*)d_in[2];
    const float* Wq = (const float*)d_in[3];
    const float* bq = (const float*)d_in[4];
    const float* Wk = (const float*)d_in[5];
    const float* bk = (const float*)d_in[6];
    const float* Wv = (const float*)d_in[7];
    const float* bv = (const float*)d_in[8];
    const float* Wo = (const float*)d_in[9];
    const float* bo = (const float*)d_in[10];
    float* out = (float*)d_out;

    float *pQ, *pK, *pV, *pA;
    cudaGetSymbolAddress((void**)&pQ, g_Q);
    cudaGetSymbolAddress((void**)&pK, g_K);
    cudaGetSymbolAddress((void**)&pV, g_V);
    cudaGetSymbolAddress((void**)&pA, g_A);

    dim3 gg(DM / 128, MTOT / 128);
    gemm_bias<<<gg, 256>>>(x, Wq, bq, pQ);
    gemm_bias<<<gg, 256>>>(y, Wk, bk, pK);
    gemm_bias<<<gg, 256>>>(y, Wv, bv, pV);

    cudaFuncSetAttribute(attn_kernel, cudaFuncAttributeMaxDynamicSharedMemorySize, ATTN_SMEM);
    dim3 ga(S / TQ, H, B);
    attn_kernel<<<ga, 256, ATTN_SMEM>>>(pQ, pK, pV, mask, pA);

    gemm_bias<<<gg, 256>>>(pA, Wo, bo, out);
}